// round 2
// baseline (speedup 1.0000x reference)
#include <cuda_runtime.h>
#include <cuda_bf16.h>

#define NB    256
#define NC    512
#define NHW   81
#define NFLAT (NC*NHW)           // 41472 per batch
#define EPSV  1e-5f

// Global scratch (allocation-free rule: __device__ arrays)
__device__ __align__(16) float g_k1[(size_t)NB * NFLAT];  // SeMCA key
__device__ __align__(16) float g_v [(size_t)NB * NFLAT];  // SeMCA value (dw3x3)

// ---------------------------------------------------------------------------
// Kernel A: per-batch. x -> smem. Computes g_k1, g_v, full SaMCA branch,
// writes out = (1-alpha)*(k1s + attn_sa*x) + alpha*k1
// smem floats: Xs[41472] | sekw[729] | sekb[81] | stage[16*648]
// ---------------------------------------------------------------------------
__global__ __launch_bounds__(512, 1)
void dmuca_kernelA(const float* __restrict__ x,
                   const float* __restrict__ alpha_p,
                   const float* __restrict__ sa_key_w,
                   const float* __restrict__ sa_key_bn,
                   const float* __restrict__ sa_att_w1,
                   const float* __restrict__ sa_att_bn,
                   const float* __restrict__ sa_att_w2,
                   const float* __restrict__ sa_att_b2,
                   const float* __restrict__ se_key_w,
                   const float* __restrict__ se_key_b,
                   const float* __restrict__ se_val_w,
                   const float* __restrict__ se_val_b,
                   float* __restrict__ out)
{
    extern __shared__ float sm[];
    float* Xs    = sm;                  // 41472
    float* sekw  = sm + NFLAT;          // 729
    float* sekb  = sekw + 729;          // 81
    float* stage = sekb + 81;           // 16 warps * 648

    const int b   = blockIdx.x;
    const int tid = threadIdx.x;
    const float* xb = x + (size_t)b * NFLAT;

    {
        const float4* xb4 = (const float4*)xb;
        float4* Xs4 = (float4*)Xs;
        #pragma unroll 4
        for (int i = tid; i < NFLAT/4; i += 512) Xs4[i] = xb4[i];
        for (int i = tid; i < 729; i += 512) sekw[i] = se_key_w[i];
        if (tid < 81) sekb[tid] = se_key_b[tid];
    }
    __syncthreads();

    const float alpha = alpha_p[0];
    const float oma   = 1.0f - alpha;

    // ---------------- Part 1: k1 and v -> global scratch --------------------
    for (int e = tid; e < NFLAT; e += 512) {
        const int ch = e / NHW;
        const int p  = e - ch * NHW;
        // k1: 9-tap depthwise conv over channel axis, per-pixel weights
        float acc = sekb[p];
        #pragma unroll
        for (int d = 0; d < 9; d++) {
            const int cc = ch + d - 4;
            if (cc >= 0 && cc < NC) acc = fmaf(sekw[p*9 + d], Xs[cc*NHW + p], acc);
        }
        g_k1[(size_t)b * NFLAT + e] = acc;

        // v: depthwise 3x3 'SAME' + bias
        const int h = p / 9, w = p - h * 9;
        float va = __ldg(se_val_b + ch);
        #pragma unroll
        for (int kh = 0; kh < 3; kh++) {
            const int hh = h + kh - 1;
            if ((unsigned)hh < 9u) {
                #pragma unroll
                for (int kw = 0; kw < 3; kw++) {
                    const int ww = w + kw - 1;
                    if ((unsigned)ww < 9u)
                        va = fmaf(__ldg(se_val_w + ch*9 + kh*3 + kw),
                                  Xs[ch*NHW + hh*9 + ww], va);
                }
            }
        }
        g_v[(size_t)b * NFLAT + e] = va;
    }

    // ---------------- Part 2: SaMCA, one head (group) per warp-iter ----------
    const int warp = tid >> 5;
    const int lane = tid & 31;
    float* ks = stage + warp * 648;     // k1s staging: 8 ch x 81 px

    for (int it = 0; it < 4; it++) {
        const int g = warp + 16 * it;      // head 0..63
        const int chbase = g * 8;

        // k1s = relu(bn(dw3x3(x))) for this head's 8 channels
        #pragma unroll
        for (int l = 0; l < 8; l++) {
            const int ch = chbase + l;
            const float gam = __ldg(sa_key_bn + ch);
            const float bet = __ldg(sa_key_bn + 512 + ch);
            const float mea = __ldg(sa_key_bn + 1024 + ch);
            const float var = __ldg(sa_key_bn + 1536 + ch);
            const float s   = gam * rsqrtf(var + EPSV);
            const float sh  = bet - mea * s;
            float wk[9];
            #pragma unroll
            for (int k = 0; k < 9; k++) wk[k] = __ldg(sa_key_w + ch*9 + k);
            for (int pp = lane; pp < 81; pp += 32) {
                const int h = pp / 9, w = pp - h * 9;
                float a = 0.f;
                #pragma unroll
                for (int kh = 0; kh < 3; kh++) {
                    const int hh = h + kh - 1;
                    if ((unsigned)hh < 9u) {
                        #pragma unroll
                        for (int kw = 0; kw < 3; kw++) {
                            const int ww = w + kw - 1;
                            if ((unsigned)ww < 9u)
                                a = fmaf(wk[kh*3+kw], Xs[ch*NHW + hh*9 + ww], a);
                        }
                    }
                }
                ks[l*81 + pp] = fmaxf(fmaf(a, s, sh), 0.f);
            }
        }
        __syncwarp();

        // logits a2b[p] = b2[g] + sum_o w2[g,o] * relu(bn(sum_l w1 * (k1s|x)))
        const float bg = __ldg(sa_att_b2 + g);
        float a2b[3] = {bg, bg, bg};
        #pragma unroll
        for (int o = 0; o < 8; o++) {
            const int oc = chbase + o;
            float w1r[16];
            #pragma unroll
            for (int i = 0; i < 16; i++) w1r[i] = __ldg(sa_att_w1 + oc*16 + i);
            const float gam = __ldg(sa_att_bn + oc);
            const float bet = __ldg(sa_att_bn + 512 + oc);
            const float mea = __ldg(sa_att_bn + 1024 + oc);
            const float var = __ldg(sa_att_bn + 1536 + oc);
            const float s2  = gam * rsqrtf(var + EPSV);
            const float sh2 = bet - mea * s2;
            const float w2v = __ldg(sa_att_w2 + oc);   // (64,8) flat == oc
            #pragma unroll
            for (int t = 0; t < 3; t++) {
                const int pp = lane + 32 * t;
                if (pp < 81) {
                    float aa = 0.f;
                    #pragma unroll
                    for (int l = 0; l < 8; l++) {
                        aa = fmaf(w1r[2*l],   ks[l*81 + pp], aa);
                        aa = fmaf(w1r[2*l+1], Xs[(chbase + l)*NHW + pp], aa);
                    }
                    aa = fmaxf(fmaf(aa, s2, sh2), 0.f);
                    a2b[t] = fmaf(w2v, aa, a2b[t]);
                }
            }
        }

        // warp softmax over 81 pixels
        float m = -1e30f;
        #pragma unroll
        for (int t = 0; t < 3; t++) { if (lane + 32*t < 81) m = fmaxf(m, a2b[t]); }
        #pragma unroll
        for (int off = 16; off > 0; off >>= 1)
            m = fmaxf(m, __shfl_xor_sync(0xffffffffu, m, off));
        float ex[3] = {0.f, 0.f, 0.f};
        float ssum = 0.f;
        #pragma unroll
        for (int t = 0; t < 3; t++) {
            const int pp = lane + 32 * t;
            if (pp < 81) { ex[t] = __expf(a2b[t] - m); ssum += ex[t]; }
        }
        #pragma unroll
        for (int off = 16; off > 0; off >>= 1)
            ssum += __shfl_xor_sync(0xffffffffu, ssum, off);
        const float inv = 1.0f / ssum;

        // out = (1-a)*(k1s + attn*x) + a*k1   (k1 recomputed from smem)
        #pragma unroll
        for (int t = 0; t < 3; t++) {
            const int pp = lane + 32 * t;
            if (pp < 81) {
                const float att = ex[t] * inv;
                #pragma unroll
                for (int l = 0; l < 8; l++) {
                    const int ch = chbase + l;
                    float k1v = sekb[pp];
                    #pragma unroll
                    for (int d = 0; d < 9; d++) {
                        const int cc = ch + d - 4;
                        if (cc >= 0 && cc < NC)
                            k1v = fmaf(sekw[pp*9 + d], Xs[cc*NHW + pp], k1v);
                    }
                    const float o2 = ks[l*81 + pp] + att * Xs[ch*NHW + pp];
                    out[(size_t)b * NFLAT + ch*NHW + pp] = oma * o2 + alpha * k1v;
                }
            }
        }
        __syncwarp();
    }
}

// ---------------------------------------------------------------------------
// Kernel B: per-batch SeMCA attention GEMM (81x162x512) + softmax + epilogue.
// Source matrix S (162 x 512): rows 0..80 = x flat, rows 81..161 = k1 flat.
// Thread tile: 9 o-rows x 8 cols; 576 threads; K streamed in 18-row tiles.
// smem floats: W1T[13122] | (pad) sbuf[9216] | a2s[4608] | w2s[729] | bnS[81] | bnH[81]
// ---------------------------------------------------------------------------
#define OFF_W1T 0
#define OFF_SRC 13124
#define OFF_A2S (OFF_SRC + 9216)      // 22340
#define OFF_W2  (OFF_A2S + 4608)      // 26948
#define OFF_BNS (OFF_W2 + 729)        // 27677
#define OFF_BNH (OFF_BNS + 81)        // 27758
#define SMEMB_FLOATS (OFF_BNH + 81)   // 27839

__global__ __launch_bounds__(576, 1)
void dmuca_kernelB(const float* __restrict__ x,
                   const float* __restrict__ alpha_p,
                   const float* __restrict__ se_att_w1,
                   const float* __restrict__ se_att_bn,
                   const float* __restrict__ se_att_w2,
                   const float* __restrict__ se_att_b2,
                   float* __restrict__ out)
{
    extern __shared__ float sm[];
    float* W1T  = sm + OFF_W1T;
    float* sbuf = sm + OFF_SRC;
    float* a2s  = sm + OFF_A2S;
    float* w2s  = sm + OFF_W2;
    float* bnS  = sm + OFF_BNS;
    float* bnH  = sm + OFF_BNH;

    const int b   = blockIdx.x;
    const int tid = threadIdx.x;
    const float* xb  = x    + (size_t)b * NFLAT;
    const float* k1b = g_k1 + (size_t)b * NFLAT;
    const float* vb  = g_v  + (size_t)b * NFLAT;

    // prologue: W1 transposed [j][o], w2, bn scale/shift, a2s init = bias
    for (int i = tid; i < 13122; i += 576) {
        const int j = i / 81, o = i - j * 81;
        W1T[i] = __ldg(se_att_w1 + o * 162 + j);
    }
    for (int i = tid; i < 729; i += 576) w2s[i] = se_att_w2[i];
    if (tid < 81) {
        const float gam = se_att_bn[tid],       bet = se_att_bn[81 + tid];
        const float mea = se_att_bn[162 + tid], var = se_att_bn[243 + tid];
        const float s = gam * rsqrtf(var + EPSV);
        bnS[tid] = s; bnH[tid] = bet - mea * s;
    }
    for (int i = tid; i < 4608; i += 576) a2s[i] = __ldg(se_att_b2 + i / 512);

    const int o_tile  = tid / 64;        // 0..8
    const int ch_tile = tid - o_tile*64; // 0..63
    const int o0  = o_tile * 9;
    const int ch0 = ch_tile * 8;

    float acc[9][8];
    #pragma unroll
    for (int a = 0; a < 9; a++)
        #pragma unroll
        for (int cc = 0; cc < 8; cc++) acc[a][cc] = 0.f;

    // K loop: 9 tiles of 18 rows
    for (int kt = 0; kt < 9; kt++) {
        __syncthreads();
        #pragma unroll
        for (int q = 0; q < 4; q++) {
            const int f4 = q * 576 + tid;        // 0..2303
            const int jr = f4 >> 7, c4 = f4 & 127;
            const int j  = kt * 18 + jr;
            const float* row = (j < 81) ? (xb + j * 512) : (k1b + (j - 81) * 512);
            ((float4*)sbuf)[jr * 128 + c4] = ((const float4*)row)[c4];
        }
        __syncthreads();

        const float4* sb4 = (const float4*)sbuf;
        #pragma unroll
        for (int jj = 0; jj < 18; jj++) {
            const int j = kt * 18 + jj;
            float wv[9];
            #pragma unroll
            for (int a = 0; a < 9; a++) wv[a] = W1T[j * 81 + o0 + a];
            const float4 sA = sb4[jj * 128 + (ch0 >> 2)];
            const float4 sB = sb4[jj * 128 + (ch0 >> 2) + 1];
            const float sv[8] = {sA.x, sA.y, sA.z, sA.w, sB.x, sB.y, sB.z, sB.w};
            #pragma unroll
            for (int a = 0; a < 9; a++)
                #pragma unroll
                for (int cc = 0; cc < 8; cc++)
                    acc[a][cc] = fmaf(wv[a], sv[cc], acc[a][cc]);
        }
    }

    // BN + relu in registers
    #pragma unroll
    for (int a = 0; a < 9; a++) {
        const float s = bnS[o0 + a], hh = bnH[o0 + a];
        #pragma unroll
        for (int cc = 0; cc < 8; cc++)
            acc[a][cc] = fmaxf(fmaf(acc[a][cc], s, hh), 0.f);
    }

    // stage-2: a2[d,col] += sum_a w2[d, o0+a] * acc[a][col]; deterministic
    // (one o-group writes per barrier phase)
    for (int ot = 0; ot < 9; ot++) {
        if (o_tile == ot) {
            #pragma unroll
            for (int d = 0; d < 9; d++) {
                float w2r[9];
                #pragma unroll
                for (int a = 0; a < 9; a++) w2r[a] = w2s[d * 81 + o0 + a];
                #pragma unroll
                for (int cc = 0; cc < 8; cc++) {
                    float pd = 0.f;
                    #pragma unroll
                    for (int a = 0; a < 9; a++) pd = fmaf(w2r[a], acc[a][cc], pd);
                    a2s[d * 512 + ch0 + cc] += pd;
                }
            }
        }
        __syncthreads();
    }

    // softmax over the 9 spectral taps, per column, in place
    if (tid < 512) {
        const int col = tid;
        float v[9], m = -1e30f;
        #pragma unroll
        for (int d = 0; d < 9; d++) { v[d] = a2s[d * 512 + col]; m = fmaxf(m, v[d]); }
        float ssum = 0.f;
        #pragma unroll
        for (int d = 0; d < 9; d++) { v[d] = __expf(v[d] - m); ssum += v[d]; }
        const float inv = 1.0f / ssum;
        #pragma unroll
        for (int d = 0; d < 9; d++) a2s[d * 512 + col] = v[d] * inv;
    }
    __syncthreads();

    // epilogue: out += alpha * sum_d attn[d,ch] * v[ch+d-4, p]
    const float alpha = alpha_p[0];
    for (int e = tid; e < NFLAT; e += 576) {
        const int ch = e / NHW;
        const int p  = e - ch * NHW;
        float s = 0.f;
        #pragma unroll
        for (int d = 0; d < 9; d++) {
            const int cc = ch + d - 4;
            if (cc >= 0 && cc < NC)
                s = fmaf(a2s[d * 512 + ch], __ldg(vb + cc * NHW + p), s);
        }
        out[(size_t)b * NFLAT + e] += alpha * s;
    }
}

extern "C" void kernel_launch(void* const* d_in, const int* in_sizes, int n_in,
                              void* d_out, int out_size) {
    const float* x         = (const float*)d_in[0];
    const float* alpha     = (const float*)d_in[1];
    const float* sa_key_w  = (const float*)d_in[2];
    const float* sa_key_bn = (const float*)d_in[3];
    const float* sa_att_w1 = (const float*)d_in[4];
    const float* sa_att_bn = (const float*)d_in[5];
    const float* sa_att_w2 = (const float*)d_in[6];
    const float* sa_att_b2 = (const float*)d_in[7];
    const float* se_key_w  = (const float*)d_in[8];
    const float* se_key_b  = (const float*)d_in[9];
    const float* se_att_w1 = (const float*)d_in[10];
    const float* se_att_bn = (const float*)d_in[11];
    const float* se_att_w2 = (const float*)d_in[12];
    const float* se_att_b2 = (const float*)d_in[13];
    const float* se_val_w  = (const float*)d_in[14];
    const float* se_val_b  = (const float*)d_in[15];
    float* out = (float*)d_out;

    const int smemA = (NFLAT + 729 + 81 + 16*648) * 4;       // 210600 B
    const int smemB = SMEMB_FLOATS * 4;                      // 111356 B
    cudaFuncSetAttribute(dmuca_kernelA,
        cudaFuncAttributeMaxDynamicSharedMemorySize, smemA);
    cudaFuncSetAttribute(dmuca_kernelB,
        cudaFuncAttributeMaxDynamicSharedMemorySize, smemB);

    dmuca_kernelA<<<NB, 512, smemA>>>(x, alpha, sa_key_w, sa_key_bn,
                                      sa_att_w1, sa_att_bn, sa_att_w2, sa_att_b2,
                                      se_key_w, se_key_b, se_val_w, se_val_b, out);
    dmuca_kernelB<<<NB, 576, smemB>>>(x, alpha, se_att_w1, se_att_bn,
                                      se_att_w2, se_att_b2, out);
}

// round 3
// speedup vs baseline: 1.0236x; 1.0236x over previous
#include <cuda_runtime.h>
#include <cuda_bf16.h>

#define NB    256
#define NC    512
#define NHW   81
#define NFLAT (NC*NHW)           // 41472 per batch
#define EPSV  1e-5f

typedef unsigned long long u64;

__device__ __forceinline__ u64 pack2(float a, float b) {
    u64 r; asm("mov.b64 %0, {%1,%2};" : "=l"(r) : "f"(a), "f"(b)); return r;
}
__device__ __forceinline__ void unpack2(u64 v, float& a, float& b) {
    asm("mov.b64 {%0,%1}, %2;" : "=f"(a), "=f"(b) : "l"(v));
}
__device__ __forceinline__ void ffma2(u64& d, u64 a, u64 b) {
    asm("fma.rn.f32x2 %0, %1, %2, %0;" : "+l"(d) : "l"(a), "l"(b));
}

// Global scratch (allocation-free rule: __device__ arrays)
__device__ __align__(16) float g_k1[(size_t)NB * NFLAT];  // SeMCA key
__device__ __align__(16) float g_v [(size_t)NB * NFLAT];  // SeMCA value (dw3x3)

// ---------------------------------------------------------------------------
// Kernel A: per-batch. x -> smem. Computes g_k1, g_v, full SaMCA branch,
// writes out = (1-alpha)*(k1s + attn_sa*x) + alpha*k1
// smem floats: Xs[41472] | sekw[729] | sekb[81] | stage[16*648]
// ---------------------------------------------------------------------------
__global__ __launch_bounds__(512, 1)
void dmuca_kernelA(const float* __restrict__ x,
                   const float* __restrict__ alpha_p,
                   const float* __restrict__ sa_key_w,
                   const float* __restrict__ sa_key_bn,
                   const float* __restrict__ sa_att_w1,
                   const float* __restrict__ sa_att_bn,
                   const float* __restrict__ sa_att_w2,
                   const float* __restrict__ sa_att_b2,
                   const float* __restrict__ se_key_w,
                   const float* __restrict__ se_key_b,
                   const float* __restrict__ se_val_w,
                   const float* __restrict__ se_val_b,
                   float* __restrict__ out)
{
    extern __shared__ float sm[];
    float* Xs    = sm;                  // 41472
    float* sekw  = sm + NFLAT;          // 729
    float* sekb  = sekw + 729;          // 81
    float* stage = sekb + 81;           // 16 warps * 648

    const int b   = blockIdx.x;
    const int tid = threadIdx.x;
    const int warp = tid >> 5;
    const int lane = tid & 31;
    const float* xb = x + (size_t)b * NFLAT;

    {
        const float4* xb4 = (const float4*)xb;
        float4* Xs4 = (float4*)Xs;
        #pragma unroll 4
        for (int i = tid; i < NFLAT/4; i += 512) Xs4[i] = xb4[i];
        for (int i = tid; i < 729; i += 512) sekw[i] = se_key_w[i];
        if (tid < 81) sekb[tid] = se_key_b[tid];
    }
    __syncthreads();

    const float alpha = alpha_p[0];
    const float oma   = 1.0f - alpha;

    // ---------------- Part 1: k1 and v -> global scratch --------------------
    // warp-per-channel: ch = ci*16 + warp; lanes cover 81 pixels (3 rounds).
    // All channel-bound predicates are warp-uniform; no integer division.
    for (int ci = 0; ci < 32; ci++) {
        const int ch = ci * 16 + warp;
        float wk[9];
        #pragma unroll
        for (int k = 0; k < 9; k++) wk[k] = __ldg(se_val_w + ch*9 + k);
        const float vbias = __ldg(se_val_b + ch);
        const float* Xc = Xs + ch * NHW;
        float* gk = g_k1 + (size_t)b * NFLAT + ch * NHW;
        float* gv = g_v  + (size_t)b * NFLAT + ch * NHW;

        #pragma unroll
        for (int t = 0; t < 3; t++) {
            const int p = lane + 32 * t;
            if (p < 81) {
                // k1: 9-tap depthwise conv over channel axis, per-pixel weights
                float acc = sekb[p];
                #pragma unroll
                for (int d = 0; d < 9; d++) {
                    const int cc = ch + d - 4;                 // warp-uniform bound
                    if (cc >= 0 && cc < NC)
                        acc = fmaf(sekw[p*9 + d], Xs[cc*NHW + p], acc);
                }
                gk[p] = acc;

                // v: depthwise 3x3 'SAME' + bias
                const int h = p / 9, w = p - h * 9;
                float va = vbias;
                #pragma unroll
                for (int kh = 0; kh < 3; kh++) {
                    const int hh = h + kh - 1;
                    if ((unsigned)hh < 9u) {
                        #pragma unroll
                        for (int kw = 0; kw < 3; kw++) {
                            const int ww = w + kw - 1;
                            if ((unsigned)ww < 9u)
                                va = fmaf(wk[kh*3+kw], Xc[hh*9 + ww], va);
                        }
                    }
                }
                gv[p] = va;
            }
        }
    }
    __syncthreads();   // Part 2 reads g_k1 written by other warps

    // ---------------- Part 2: SaMCA, one head (group) per warp-iter ----------
    float* ks = stage + warp * 648;     // k1s staging: 8 ch x 81 px

    for (int it = 0; it < 4; it++) {
        const int g = warp + 16 * it;      // head 0..63
        const int chbase = g * 8;

        // k1s = relu(bn(dw3x3(x))) for this head's 8 channels
        #pragma unroll
        for (int l = 0; l < 8; l++) {
            const int ch = chbase + l;
            const float gam = __ldg(sa_key_bn + ch);
            const float bet = __ldg(sa_key_bn + 512 + ch);
            const float mea = __ldg(sa_key_bn + 1024 + ch);
            const float var = __ldg(sa_key_bn + 1536 + ch);
            const float s   = gam * rsqrtf(var + EPSV);
            const float sh  = bet - mea * s;
            float wk[9];
            #pragma unroll
            for (int k = 0; k < 9; k++) wk[k] = __ldg(sa_key_w + ch*9 + k);
            for (int pp = lane; pp < 81; pp += 32) {
                const int h = pp / 9, w = pp - h * 9;
                float a = 0.f;
                #pragma unroll
                for (int kh = 0; kh < 3; kh++) {
                    const int hh = h + kh - 1;
                    if ((unsigned)hh < 9u) {
                        #pragma unroll
                        for (int kw = 0; kw < 3; kw++) {
                            const int ww = w + kw - 1;
                            if ((unsigned)ww < 9u)
                                a = fmaf(wk[kh*3+kw], Xs[ch*NHW + hh*9 + ww], a);
                        }
                    }
                }
                ks[l*81 + pp] = fmaxf(fmaf(a, s, sh), 0.f);
            }
        }
        __syncwarp();

        // logits a2b[p] = b2[g] + sum_o w2[g,o] * relu(bn(sum_l w1 * (k1s|x)))
        const float bg = __ldg(sa_att_b2 + g);
        float a2b[3] = {bg, bg, bg};
        #pragma unroll
        for (int o = 0; o < 8; o++) {
            const int oc = chbase + o;
            float w1r[16];
            #pragma unroll
            for (int i = 0; i < 16; i++) w1r[i] = __ldg(sa_att_w1 + oc*16 + i);
            const float gam = __ldg(sa_att_bn + oc);
            const float bet = __ldg(sa_att_bn + 512 + oc);
            const float mea = __ldg(sa_att_bn + 1024 + oc);
            const float var = __ldg(sa_att_bn + 1536 + oc);
            const float s2  = gam * rsqrtf(var + EPSV);
            const float sh2 = bet - mea * s2;
            const float w2v = __ldg(sa_att_w2 + oc);   // (64,8) flat == oc
            #pragma unroll
            for (int t = 0; t < 3; t++) {
                const int pp = lane + 32 * t;
                if (pp < 81) {
                    float aa = 0.f;
                    #pragma unroll
                    for (int l = 0; l < 8; l++) {
                        aa = fmaf(w1r[2*l],   ks[l*81 + pp], aa);
                        aa = fmaf(w1r[2*l+1], Xs[(chbase + l)*NHW + pp], aa);
                    }
                    aa = fmaxf(fmaf(aa, s2, sh2), 0.f);
                    a2b[t] = fmaf(w2v, aa, a2b[t]);
                }
            }
        }

        // warp softmax over 81 pixels
        float m = -1e30f;
        #pragma unroll
        for (int t = 0; t < 3; t++) { if (lane + 32*t < 81) m = fmaxf(m, a2b[t]); }
        #pragma unroll
        for (int off = 16; off > 0; off >>= 1)
            m = fmaxf(m, __shfl_xor_sync(0xffffffffu, m, off));
        float ex[3] = {0.f, 0.f, 0.f};
        float ssum = 0.f;
        #pragma unroll
        for (int t = 0; t < 3; t++) {
            const int pp = lane + 32 * t;
            if (pp < 81) { ex[t] = __expf(a2b[t] - m); ssum += ex[t]; }
        }
        #pragma unroll
        for (int off = 16; off > 0; off >>= 1)
            ssum += __shfl_xor_sync(0xffffffffu, ssum, off);
        const float inv = 1.0f / ssum;

        // out = (1-a)*(k1s + attn*x) + a*k1   (k1 read back from g_k1, L2 hit)
        #pragma unroll
        for (int t = 0; t < 3; t++) {
            const int pp = lane + 32 * t;
            if (pp < 81) {
                const float att = ex[t] * inv;
                #pragma unroll
                for (int l = 0; l < 8; l++) {
                    const int ch = chbase + l;
                    const float k1v = g_k1[(size_t)b * NFLAT + ch*NHW + pp];
                    const float o2 = ks[l*81 + pp] + att * Xs[ch*NHW + pp];
                    out[(size_t)b * NFLAT + ch*NHW + pp] = oma * o2 + alpha * k1v;
                }
            }
        }
        __syncwarp();
    }
}

// ---------------------------------------------------------------------------
// Kernel B: per-batch SeMCA attention GEMM (81x162x512) + softmax + epilogue.
// Source matrix S (162 x 512): rows 0..80 = x flat, rows 81..161 = k1 flat.
// Thread tile: 9 o-rows x 8 cols (packed f32x2); K in 18-row double-buffered
// tiles. smem: W1T[13124] | sbuf[2*9216] | a2s[4608] | w2s[729] | bnS/bnH[162]
// ---------------------------------------------------------------------------
#define OFF_W1T 0
#define OFF_SRC 13124
#define OFF_A2S (OFF_SRC + 18432)     // 31556
#define OFF_W2  (OFF_A2S + 4608)      // 36164
#define OFF_BNS (OFF_W2 + 729)        // 36893
#define OFF_BNH (OFF_BNS + 81)        // 36974
#define SMEMB_FLOATS (OFF_BNH + 81)   // 37055

__global__ __launch_bounds__(576, 1)
void dmuca_kernelB(const float* __restrict__ x,
                   const float* __restrict__ alpha_p,
                   const float* __restrict__ se_att_w1,
                   const float* __restrict__ se_att_bn,
                   const float* __restrict__ se_att_w2,
                   const float* __restrict__ se_att_b2,
                   float* __restrict__ out)
{
    extern __shared__ float sm[];
    float* W1T  = sm + OFF_W1T;
    float* sbuf = sm + OFF_SRC;
    float* a2s  = sm + OFF_A2S;
    float* w2s  = sm + OFF_W2;
    float* bnS  = sm + OFF_BNS;
    float* bnH  = sm + OFF_BNH;

    const int b   = blockIdx.x;
    const int tid = threadIdx.x;
    const float* xb  = x    + (size_t)b * NFLAT;
    const float* k1b = g_k1 + (size_t)b * NFLAT;
    const float* vb  = g_v  + (size_t)b * NFLAT;

    // prologue: W1 transposed [j][o], w2, bn scale/shift, a2s init = bias
    for (int i = tid; i < 13122; i += 576) {
        const int j = i / 81, o = i - j * 81;
        W1T[i] = __ldg(se_att_w1 + o * 162 + j);
    }
    for (int i = tid; i < 729; i += 576) w2s[i] = se_att_w2[i];
    if (tid < 81) {
        const float gam = se_att_bn[tid],       bet = se_att_bn[81 + tid];
        const float mea = se_att_bn[162 + tid], var = se_att_bn[243 + tid];
        const float s = gam * rsqrtf(var + EPSV);
        bnS[tid] = s; bnH[tid] = bet - mea * s;
    }
    for (int i = tid; i < 4608; i += 576) a2s[i] = __ldg(se_att_b2 + i / 512);

    const int o_tile  = tid / 64;        // 0..8
    const int ch_tile = tid - o_tile*64; // 0..63
    const int o0  = o_tile * 9;
    const int ch0 = ch_tile * 8;

    u64 acc2[9][4];
    #pragma unroll
    for (int a = 0; a < 9; a++)
        #pragma unroll
        for (int q = 0; q < 4; q++) acc2[a][q] = 0ULL;

    // preload tile 0 into registers
    float4 r[4];
    #pragma unroll
    for (int q = 0; q < 4; q++) {
        const int f4 = q * 576 + tid;        // 0..2303
        const int jr = f4 >> 7, c4 = f4 & 127;
        const float* row = (jr < 81) ? (xb + jr * 512) : (k1b + (jr - 81) * 512);
        r[q] = ((const float4*)row)[c4];
    }

    // K loop: 9 tiles of 18 rows, double-buffered, one sync per iteration
    for (int kt = 0; kt < 9; kt++) {
        float* sb = sbuf + (kt & 1) * 9216;
        #pragma unroll
        for (int q = 0; q < 4; q++) {
            const int f4 = q * 576 + tid;
            const int jr = f4 >> 7, c4 = f4 & 127;
            ((float4*)sb)[jr * 128 + c4] = r[q];
        }
        __syncthreads();

        if (kt < 8) {
            #pragma unroll
            for (int q = 0; q < 4; q++) {
                const int f4 = q * 576 + tid;
                const int jr = f4 >> 7, c4 = f4 & 127;
                const int j  = (kt + 1) * 18 + jr;
                const float* row = (j < 81) ? (xb + j * 512) : (k1b + (j - 81) * 512);
                r[q] = ((const float4*)row)[c4];
            }
        }

        const ulonglong2* sb2 = (const ulonglong2*)sb;   // 128 per row
        #pragma unroll
        for (int jj = 0; jj < 18; jj++) {
            const int j = kt * 18 + jj;
            u64 wv2[9];
            #pragma unroll
            for (int a = 0; a < 9; a++) {
                const float wv = W1T[j * 81 + o0 + a];
                wv2[a] = pack2(wv, wv);
            }
            const ulonglong2 pA = sb2[jj * 128 + (ch0 >> 2)];
            const ulonglong2 pB = sb2[jj * 128 + (ch0 >> 2) + 1];
            #pragma unroll
            for (int a = 0; a < 9; a++) {
                ffma2(acc2[a][0], wv2[a], pA.x);
                ffma2(acc2[a][1], wv2[a], pA.y);
                ffma2(acc2[a][2], wv2[a], pB.x);
                ffma2(acc2[a][3], wv2[a], pB.y);
            }
        }
    }

    // unpack + BN + relu
    float acc[9][8];
    #pragma unroll
    for (int a = 0; a < 9; a++) {
        const float s = bnS[o0 + a], hh = bnH[o0 + a];
        #pragma unroll
        for (int q = 0; q < 4; q++) {
            float lo, hi;
            unpack2(acc2[a][q], lo, hi);
            acc[a][2*q]   = fmaxf(fmaf(lo, s, hh), 0.f);
            acc[a][2*q+1] = fmaxf(fmaf(hi, s, hh), 0.f);
        }
    }

    // stage-2: a2[d,col] += sum_a w2[d, o0+a] * acc[a][col]; deterministic
    for (int ot = 0; ot < 9; ot++) {
        if (o_tile == ot) {
            #pragma unroll
            for (int d = 0; d < 9; d++) {
                float w2r[9];
                #pragma unroll
                for (int a = 0; a < 9; a++) w2r[a] = w2s[d * 81 + o0 + a];
                #pragma unroll
                for (int cc = 0; cc < 8; cc++) {
                    float pd = 0.f;
                    #pragma unroll
                    for (int a = 0; a < 9; a++) pd = fmaf(w2r[a], acc[a][cc], pd);
                    a2s[d * 512 + ch0 + cc] += pd;
                }
            }
        }
        __syncthreads();
    }

    // softmax over the 9 spectral taps, per column, in place
    if (tid < 512) {
        const int col = tid;
        float v[9], m = -1e30f;
        #pragma unroll
        for (int d = 0; d < 9; d++) { v[d] = a2s[d * 512 + col]; m = fmaxf(m, v[d]); }
        float ssum = 0.f;
        #pragma unroll
        for (int d = 0; d < 9; d++) { v[d] = __expf(v[d] - m); ssum += v[d]; }
        const float inv = 1.0f / ssum;
        #pragma unroll
        for (int d = 0; d < 9; d++) a2s[d * 512 + col] = v[d] * inv;
    }
    __syncthreads();

    // epilogue: out += alpha * sum_d attn[d,ch] * v[ch+d-4, p]
    const float alpha = alpha_p[0];
    for (int e = tid; e < NFLAT; e += 576) {
        const int ch = e / NHW;
        const int p  = e - ch * NHW;
        float s = 0.f;
        #pragma unroll
        for (int d = 0; d < 9; d++) {
            const int cc = ch + d - 4;
            if (cc >= 0 && cc < NC)
                s = fmaf(a2s[d * 512 + ch], __ldg(vb + cc * NHW + p), s);
        }
        out[(size_t)b * NFLAT + e] += alpha * s;
    }
}

extern "C" void kernel_launch(void* const* d_in, const int* in_sizes, int n_in,
                              void* d_out, int out_size) {
    const float* x         = (const float*)d_in[0];
    const float* alpha     = (const float*)d_in[1];
    const float* sa_key_w  = (const float*)d_in[2];
    const float* sa_key_bn = (const float*)d_in[3];
    const float* sa_att_w1 = (const float*)d_in[4];
    const float* sa_att_bn = (const float*)d_in[5];
    const float* sa_att_w2 = (const float*)d_in[6];
    const float* sa_att_b2 = (const float*)d_in[7];
    const float* se_key_w  = (const float*)d_in[8];
    const float* se_key_b  = (const float*)d_in[9];
    const float* se_att_w1 = (const float*)d_in[10];
    const float* se_att_bn = (const float*)d_in[11];
    const float* se_att_w2 = (const float*)d_in[12];
    const float* se_att_b2 = (const float*)d_in[13];
    const float* se_val_w  = (const float*)d_in[14];
    const float* se_val_b  = (const float*)d_in[15];
    float* out = (float*)d_out;

    const int smemA = (NFLAT + 729 + 81 + 16*648) * 4;       // 210600 B
    const int smemB = SMEMB_FLOATS * 4;                      // 148220 B
    cudaFuncSetAttribute(dmuca_kernelA,
        cudaFuncAttributeMaxDynamicSharedMemorySize, smemA);
    cudaFuncSetAttribute(dmuca_kernelB,
        cudaFuncAttributeMaxDynamicSharedMemorySize, smemB);

    dmuca_kernelA<<<NB, 512, smemA>>>(x, alpha, sa_key_w, sa_key_bn,
                                      sa_att_w1, sa_att_bn, sa_att_w2, sa_att_b2,
                                      se_key_w, se_key_b, se_val_w, se_val_b, out);
    dmuca_kernelB<<<NB, 576, smemB>>>(x, alpha, se_att_w1, se_att_bn,
                                      se_att_w2, se_att_b2, out);
}

// round 5
// speedup vs baseline: 1.2810x; 1.2515x over previous
#include <cuda_runtime.h>
#include <cuda_bf16.h>

#define NB    256
#define NC    512
#define NHW   81
#define NFLAT (NC*NHW)           // 41472 per batch
#define EPSV  1e-5f

typedef unsigned long long u64;

__device__ __forceinline__ u64 pack2(float a, float b) {
    u64 r; asm("mov.b64 %0, {%1,%2};" : "=l"(r) : "f"(a), "f"(b)); return r;
}
__device__ __forceinline__ void unpack2(u64 v, float& a, float& b) {
    asm("mov.b64 {%0,%1}, %2;" : "=f"(a), "=f"(b) : "l"(v));
}
__device__ __forceinline__ void ffma2(u64& d, u64 a, u64 b) {
    asm("fma.rn.f32x2 %0, %1, %2, %0;" : "+l"(d) : "l"(a), "l"(b));
}

// Global scratch (allocation-free rule: __device__ arrays)
__device__ __align__(16) float g_k1[(size_t)NB * NFLAT];  // SeMCA key
__device__ __align__(16) float g_v [(size_t)NB * NFLAT];  // SeMCA value (dw3x3)

// ---------------------------------------------------------------------------
// Kernel A (banded): grid = NB*8. Each CTA: one batch x one 64-channel band
// (+4 halo channels each side, zero-filled at x edges). 8 warps = 8 heads.
// Computes g_k1, g_v, full SaMCA head pipeline, writes
//   out = (1-alpha)*(k1s + attn_sa*x) + alpha*k1
// smem floats: Xs[72*81=5832] | sekw[729] | sekb[81] | stage[8*1296]
// ---------------------------------------------------------------------------
#define A_SMEM_FLOATS (5832 + 729 + 81 + 8*1296)   // 17010

__global__ __launch_bounds__(256, 3)
void dmuca_kernelA(const float* __restrict__ x,
                   const float* __restrict__ alpha_p,
                   const float* __restrict__ sa_key_w,
                   const float* __restrict__ sa_key_bn,
                   const float* __restrict__ sa_att_w1,
                   const float* __restrict__ sa_att_bn,
                   const float* __restrict__ sa_att_w2,
                   const float* __restrict__ sa_att_b2,
                   const float* __restrict__ se_key_w,
                   const float* __restrict__ se_key_b,
                   const float* __restrict__ se_val_w,
                   const float* __restrict__ se_val_b,
                   float* __restrict__ out)
{
    extern __shared__ float sm[];
    float* Xs    = sm;                 // 5832 (72 rows x 81)
    float* sekw  = sm + 5832;          // 729
    float* sekb  = sekw + 729;         // 81
    float* stage = sekb + 81;          // 8 warps * 1296 (ks 648 | k1st 648)

    const int bb   = blockIdx.x;
    const int b    = bb >> 3;
    const int band = bb & 7;
    const int chlo = band << 6;        // band*64
    const int tid  = threadIdx.x;
    const int warp = tid >> 5;
    const int lane = tid & 31;
    const float* xb = x + (size_t)b * NFLAT;

    // load band + halo (zero-fill past x edges)
    {
        const int gbase = (chlo - 4) * NHW;
        for (int i = tid; i < 5832; i += 256) {
            const int g = gbase + i;
            Xs[i] = ((unsigned)g < (unsigned)NFLAT) ? xb[g] : 0.f;
        }
        for (int i = tid; i < 729; i += 256) sekw[i] = se_key_w[i];
        if (tid < 81) sekb[tid] = se_key_b[tid];
    }
    __syncthreads();

    const float alpha = alpha_p[0];
    const float oma   = 1.0f - alpha;

    const int g_head = (chlo >> 3) + warp;   // head id 0..63
    const int chbase = chlo + warp * 8;      // head's first channel
    float* ks   = stage + warp * 1296;       // k1s: 8ch x 81
    float* k1st = ks + 648;                  // k1 : 8ch x 81

    // ---- Part 1: k1, v (to global) + k1s (to stage) for this head's 8 ch ----
    #pragma unroll
    for (int l = 0; l < 8; l++) {
        const int ch = chbase + l;
        const int lr = warp*8 + l + 4;       // local Xs row of ch
        const float* Xc = Xs + lr * NHW;
        float wkv[9], wks[9];
        #pragma unroll
        for (int k = 0; k < 9; k++) wkv[k] = __ldg(se_val_w + ch*9 + k);
        #pragma unroll
        for (int k = 0; k < 9; k++) wks[k] = __ldg(sa_key_w + ch*9 + k);
        const float vbias = __ldg(se_val_b + ch);
        const float gam = __ldg(sa_key_bn + ch);
        const float bet = __ldg(sa_key_bn + 512 + ch);
        const float mea = __ldg(sa_key_bn + 1024 + ch);
        const float var = __ldg(sa_key_bn + 1536 + ch);
        const float s   = gam * rsqrtf(var + EPSV);
        const float sh  = bet - mea * s;

        float* gk = g_k1 + (size_t)b * NFLAT + ch * NHW;
        float* gv = g_v  + (size_t)b * NFLAT + ch * NHW;

        #pragma unroll
        for (int t = 0; t < 3; t++) {
            const int p = lane + 32 * t;
            if (p < 81) {
                // k1: 9-tap conv over channel axis (halo zero-filled)
                float acc = sekb[p];
                #pragma unroll
                for (int d = 0; d < 9; d++)
                    acc = fmaf(sekw[p*9 + d], Xs[(lr - 4 + d)*NHW + p], acc);
                gk[p] = acc;
                k1st[l*81 + p] = acc;

                // v (dw3x3+bias) and sa-key (dw3x3) share the 3x3 window
                const int h = p / 9, w = p - h * 9;
                float va = vbias, sa = 0.f;
                #pragma unroll
                for (int kh = 0; kh < 3; kh++) {
                    const int hh = h + kh - 1;
                    if ((unsigned)hh < 9u) {
                        #pragma unroll
                        for (int kw = 0; kw < 3; kw++) {
                            const int ww = w + kw - 1;
                            if ((unsigned)ww < 9u) {
                                const float xv = Xc[hh*9 + ww];
                                va = fmaf(wkv[kh*3+kw], xv, va);
                                sa = fmaf(wks[kh*3+kw], xv, sa);
                            }
                        }
                    }
                }
                gv[p] = va;
                ks[l*81 + p] = fmaxf(fmaf(sa, s, sh), 0.f);
            }
        }
    }
    __syncwarp();

    // ---- Part 2: head attention logits + softmax + epilogue -----------------
    const float bg = __ldg(sa_att_b2 + g_head);
    float a2b[3] = {bg, bg, bg};
    #pragma unroll
    for (int o = 0; o < 8; o++) {
        const int oc = chbase + o;
        float w1r[16];
        #pragma unroll
        for (int i = 0; i < 16; i++) w1r[i] = __ldg(sa_att_w1 + oc*16 + i);
        const float gam = __ldg(sa_att_bn + oc);
        const float bet = __ldg(sa_att_bn + 512 + oc);
        const float mea = __ldg(sa_att_bn + 1024 + oc);
        const float var = __ldg(sa_att_bn + 1536 + oc);
        const float s2  = gam * rsqrtf(var + EPSV);
        const float sh2 = bet - mea * s2;
        const float w2v = __ldg(sa_att_w2 + oc);   // (64,8) flat == oc
        #pragma unroll
        for (int t = 0; t < 3; t++) {
            const int pp = lane + 32 * t;
            if (pp < 81) {
                float aa = 0.f;
                #pragma unroll
                for (int l = 0; l < 8; l++) {
                    aa = fmaf(w1r[2*l],   ks[l*81 + pp], aa);
                    aa = fmaf(w1r[2*l+1], Xs[(warp*8 + l + 4)*NHW + pp], aa);
                }
                aa = fmaxf(fmaf(aa, s2, sh2), 0.f);
                a2b[t] = fmaf(w2v, aa, a2b[t]);
            }
        }
    }

    // warp softmax over 81 pixels
    float m = -1e30f;
    #pragma unroll
    for (int t = 0; t < 3; t++) { if (lane + 32*t < 81) m = fmaxf(m, a2b[t]); }
    #pragma unroll
    for (int off = 16; off > 0; off >>= 1)
        m = fmaxf(m, __shfl_xor_sync(0xffffffffu, m, off));
    float ex[3] = {0.f, 0.f, 0.f};
    float ssum = 0.f;
    #pragma unroll
    for (int t = 0; t < 3; t++) {
        const int pp = lane + 32 * t;
        if (pp < 81) { ex[t] = __expf(a2b[t] - m); ssum += ex[t]; }
    }
    #pragma unroll
    for (int off = 16; off > 0; off >>= 1)
        ssum += __shfl_xor_sync(0xffffffffu, ssum, off);
    const float inv = 1.0f / ssum;

    // out = (1-a)*(k1s + attn*x) + a*k1
    #pragma unroll
    for (int t = 0; t < 3; t++) {
        const int pp = lane + 32 * t;
        if (pp < 81) {
            const float att = ex[t] * inv;
            #pragma unroll
            for (int l = 0; l < 8; l++) {
                const int ch = chbase + l;
                const float o2 = ks[l*81 + pp]
                               + att * Xs[(warp*8 + l + 4)*NHW + pp];
                out[(size_t)b * NFLAT + ch*NHW + pp]
                    = oma * o2 + alpha * k1st[l*81 + pp];
            }
        }
    }
}

// ---------------------------------------------------------------------------
// Kernel B: grid = NB*2 (batch x column-half). Per CTA: 81x162x256 GEMM in
// 3 o-slices of 27 rows (thread tile 3o x 4ch, 12 acc regs -> 2 CTAs/SM),
// BN+relu, w2 contraction into a2s, 9-tap softmax, spectral-window epilogue.
// smem floats: W1T[13122+2] | sbuf[2*4608] | a2s[9*256] | w2s[729] | bn[162]
// ---------------------------------------------------------------------------
#define OFFB_W1T 0
#define OFFB_SRC 13124
#define OFFB_A2S (OFFB_SRC + 9216)     // 22340
#define OFFB_W2  (OFFB_A2S + 2304)     // 24644
#define OFFB_BNS (OFFB_W2 + 729)       // 25373
#define OFFB_BNH (OFFB_BNS + 81)       // 25454
#define B_SMEM_FLOATS (OFFB_BNH + 81)  // 25535

__global__ __launch_bounds__(576, 2)
void dmuca_kernelB(const float* __restrict__ x,
                   const float* __restrict__ alpha_p,
                   const float* __restrict__ se_att_w1,
                   const float* __restrict__ se_att_bn,
                   const float* __restrict__ se_att_w2,
                   const float* __restrict__ se_att_b2,
                   float* __restrict__ out)
{
    extern __shared__ float sm[];
    float* W1T  = sm + OFFB_W1T;
    float* sbuf = sm + OFFB_SRC;
    float* a2s  = sm + OFFB_A2S;
    float* w2s  = sm + OFFB_W2;
    float* bnS  = sm + OFFB_BNS;
    float* bnH  = sm + OFFB_BNH;

    const int bx  = blockIdx.x;
    const int b   = bx >> 1;
    const int hf  = bx & 1;
    const int cbase = hf << 8;          // 0 or 256
    const int tid = threadIdx.x;
    const float* xb  = x    + (size_t)b * NFLAT + cbase;
    const float* k1b = g_k1 + (size_t)b * NFLAT + cbase;
    const float* vb  = g_v  + (size_t)b * NFLAT;

    // prologue
    for (int i = tid; i < 13122; i += 576) {
        const int j = i / 81, o = i - j * 81;
        W1T[i] = __ldg(se_att_w1 + o * 162 + j);
    }
    for (int i = tid; i < 729; i += 576) w2s[i] = se_att_w2[i];
    if (tid < 81) {
        const float gam = se_att_bn[tid],       bet = se_att_bn[81 + tid];
        const float mea = se_att_bn[162 + tid], var = se_att_bn[243 + tid];
        const float s = gam * rsqrtf(var + EPSV);
        bnS[tid] = s; bnH[tid] = bet - mea * s;
    }
    for (int i = tid; i < 2304; i += 576) a2s[i] = __ldg(se_att_b2 + (i >> 8));

    const int o_tid = tid >> 6;          // 0..8
    const int ch0   = (tid & 63) << 2;   // 0..252 (local col)

    // 3 o-slices of 27 rows
    for (int sl = 0; sl < 3; sl++) {
        const int ob = sl * 27 + o_tid * 3;    // this thread's 3 o-rows

        u64 acc2[3][2];
        #pragma unroll
        for (int a = 0; a < 3; a++) { acc2[a][0] = 0ULL; acc2[a][1] = 0ULL; }

        // prefetch tile 0 (rows are this half's 256 cols of x|k1)
        float4 r0, r1;
        {
            const int f0 = tid, f1 = 576 + tid;          // 0..1151
            const int jr0 = f0 >> 6, c0 = f0 & 63;
            const int jr1 = f1 >> 6, c1 = f1 & 63;
            const float* row0 = (jr0 < 81) ? (xb + jr0*512) : (k1b + (jr0-81)*512);
            const float* row1 = (jr1 < 81) ? (xb + jr1*512) : (k1b + (jr1-81)*512);
            r0 = ((const float4*)row0)[c0];
            r1 = ((const float4*)row1)[c1];
        }

        for (int kt = 0; kt < 9; kt++) {
            float* sb = sbuf + (kt & 1) * 4608;
            {
                const int f0 = tid, f1 = 576 + tid;
                ((float4*)sb)[(f0 >> 6) * 64 + (f0 & 63)] = r0;
                ((float4*)sb)[(f1 >> 6) * 64 + (f1 & 63)] = r1;
            }
            __syncthreads();

            if (kt < 8) {
                const int f0 = tid, f1 = 576 + tid;
                const int j0 = (kt+1)*18 + (f0 >> 6), c0 = f0 & 63;
                const int j1 = (kt+1)*18 + (f1 >> 6), c1 = f1 & 63;
                const float* row0 = (j0 < 81) ? (xb + j0*512) : (k1b + (j0-81)*512);
                const float* row1 = (j1 < 81) ? (xb + j1*512) : (k1b + (j1-81)*512);
                r0 = ((const float4*)row0)[c0];
                r1 = ((const float4*)row1)[c1];
            }

            const ulonglong2* sb2 = (const ulonglong2*)sb;   // 64 u64x2 per 256f row
            #pragma unroll
            for (int jj = 0; jj < 18; jj++) {
                const int j = kt * 18 + jj;
                const ulonglong2 pA = sb2[jj * 64 + (ch0 >> 2)];
                #pragma unroll
                for (int a = 0; a < 3; a++) {
                    const float wv = W1T[j * 81 + ob + a];
                    const u64 wv2 = pack2(wv, wv);
                    ffma2(acc2[a][0], wv2, pA.x);
                    ffma2(acc2[a][1], wv2, pA.y);
                }
            }
        }

        // BN + relu
        float accf[3][4];
        #pragma unroll
        for (int a = 0; a < 3; a++) {
            const float s = bnS[ob + a], hh = bnH[ob + a];
            float lo, hi;
            unpack2(acc2[a][0], lo, hi);
            accf[a][0] = fmaxf(fmaf(lo, s, hh), 0.f);
            accf[a][1] = fmaxf(fmaf(hi, s, hh), 0.f);
            unpack2(acc2[a][1], lo, hi);
            accf[a][2] = fmaxf(fmaf(lo, s, hh), 0.f);
            accf[a][3] = fmaxf(fmaf(hi, s, hh), 0.f);
        }

        // stage-2: a2s[d, col] += sum_a w2[d, ob+a]*accf[a][col], phased
        for (int ot = 0; ot < 9; ot++) {
            if (o_tid == ot) {
                #pragma unroll
                for (int d = 0; d < 9; d++) {
                    float w2r[3];
                    #pragma unroll
                    for (int a = 0; a < 3; a++) w2r[a] = w2s[d*81 + ob + a];
                    #pragma unroll
                    for (int cc = 0; cc < 4; cc++) {
                        float pd = w2r[0]*accf[0][cc];
                        pd = fmaf(w2r[1], accf[1][cc], pd);
                        pd = fmaf(w2r[2], accf[2][cc], pd);
                        a2s[d*256 + ch0 + cc] += pd;
                    }
                }
            }
            __syncthreads();
        }
    }

    // softmax over the 9 spectral taps, per column, in place
    if (tid < 256) {
        const int col = tid;
        float v[9], m = -1e30f;
        #pragma unroll
        for (int d = 0; d < 9; d++) { v[d] = a2s[d*256 + col]; m = fmaxf(m, v[d]); }
        float ssum = 0.f;
        #pragma unroll
        for (int d = 0; d < 9; d++) { v[d] = __expf(v[d] - m); ssum += v[d]; }
        const float inv = 1.0f / ssum;
        #pragma unroll
        for (int d = 0; d < 9; d++) a2s[d*256 + col] = v[d] * inv;
    }
    __syncthreads();

    // epilogue: out += alpha * sum_d attn[d,ch] * v[ch+d-4, p]
    const float alpha = alpha_p[0];
    float* outb = out + (size_t)b * NFLAT + (size_t)cbase * NHW;
    for (int e = tid; e < 256 * NHW; e += 576) {
        const int chl = e / 81;
        const int p   = e - chl * 81;
        const int ch  = cbase + chl;
        float s = 0.f;
        #pragma unroll
        for (int d = 0; d < 9; d++) {
            const int cc = ch + d - 4;
            if (cc >= 0 && cc < NC)
                s = fmaf(a2s[d*256 + chl], __ldg(vb + cc*NHW + p), s);
        }
        outb[e] += alpha * s;
    }
}

extern "C" void kernel_launch(void* const* d_in, const int* in_sizes, int n_in,
                              void* d_out, int out_size) {
    const float* x         = (const float*)d_in[0];
    const float* alpha     = (const float*)d_in[1];
    const float* sa_key_w  = (const float*)d_in[2];
    const float* sa_key_bn = (const float*)d_in[3];
    const float* sa_att_w1 = (const float*)d_in[4];
    const float* sa_att_bn = (const float*)d_in[5];
    const float* sa_att_w2 = (const float*)d_in[6];
    const float* sa_att_b2 = (const float*)d_in[7];
    const float* se_key_w  = (const float*)d_in[8];
    const float* se_key_b  = (const float*)d_in[9];
    const float* se_att_w1 = (const float*)d_in[10];
    const float* se_att_bn = (const float*)d_in[11];
    const float* se_att_w2 = (const float*)d_in[12];
    const float* se_att_b2 = (const float*)d_in[13];
    const float* se_val_w  = (const float*)d_in[14];
    const float* se_val_b  = (const float*)d_in[15];
    float* out = (float*)d_out;

    const int smemA = A_SMEM_FLOATS * 4;     // 68040 B
    const int smemB = B_SMEM_FLOATS * 4;     // 102140 B
    cudaFuncSetAttribute(dmuca_kernelA,
        cudaFuncAttributeMaxDynamicSharedMemorySize, smemA);
    cudaFuncSetAttribute(dmuca_kernelB,
        cudaFuncAttributeMaxDynamicSharedMemorySize, smemB);

    dmuca_kernelA<<<NB*8, 256, smemA>>>(x, alpha, sa_key_w, sa_key_bn,
                                        sa_att_w1, sa_att_bn, sa_att_w2, sa_att_b2,
                                        se_key_w, se_key_b, se_val_w, se_val_b, out);
    dmuca_kernelB<<<NB*2, 576, smemB>>>(x, alpha, se_att_w1, se_att_bn,
                                        se_att_w2, se_att_b2, out);
}

// round 6
// speedup vs baseline: 1.3040x; 1.0179x over previous
#include <cuda_runtime.h>
#include <cuda_bf16.h>
#include <cstdint>

#define NB    256
#define NC    512
#define NHW   81
#define NFLAT (NC*NHW)           // 41472 per batch
#define EPSV  1e-5f

typedef unsigned long long u64;

__device__ __forceinline__ u64 pack2(float a, float b) {
    u64 r; asm("mov.b64 %0, {%1,%2};" : "=l"(r) : "f"(a), "f"(b)); return r;
}
__device__ __forceinline__ void unpack2(u64 v, float& a, float& b) {
    asm("mov.b64 {%0,%1}, %2;" : "=f"(a), "=f"(b) : "l"(v));
}
__device__ __forceinline__ void ffma2(u64& d, u64 a, u64 b) {
    asm("fma.rn.f32x2 %0, %1, %2, %0;" : "+l"(d) : "l"(a), "l"(b));
}
__device__ __forceinline__ void cp_async16(uint32_t s, const void* g) {
    asm volatile("cp.async.ca.shared.global [%0], [%1], 16;" :: "r"(s), "l"(g));
}
__device__ __forceinline__ void cp_commit() {
    asm volatile("cp.async.commit_group;");
}
template<int N>
__device__ __forceinline__ void cp_wait() {
    asm volatile("cp.async.wait_group %0;" :: "n"(N));
}

// Global scratch (allocation-free rule: __device__ arrays)
__device__ __align__(16) float g_k1[(size_t)NB * NFLAT];  // SeMCA key
__device__ __align__(16) float g_v [(size_t)NB * NFLAT];  // SeMCA value (dw3x3)

// ---------------------------------------------------------------------------
// Kernel A (banded): grid = NB*8. Each CTA: one batch x one 64-channel band
// (+4 halo channels each side, zero-filled at x edges). 8 warps = 8 heads.
// (unchanged from round 5)
// ---------------------------------------------------------------------------
#define A_SMEM_FLOATS (5832 + 729 + 81 + 8*1296)   // 17010

__global__ __launch_bounds__(256, 3)
void dmuca_kernelA(const float* __restrict__ x,
                   const float* __restrict__ alpha_p,
                   const float* __restrict__ sa_key_w,
                   const float* __restrict__ sa_key_bn,
                   const float* __restrict__ sa_att_w1,
                   const float* __restrict__ sa_att_bn,
                   const float* __restrict__ sa_att_w2,
                   const float* __restrict__ sa_att_b2,
                   const float* __restrict__ se_key_w,
                   const float* __restrict__ se_key_b,
                   const float* __restrict__ se_val_w,
                   const float* __restrict__ se_val_b,
                   float* __restrict__ out)
{
    extern __shared__ float sm[];
    float* Xs    = sm;                 // 5832 (72 rows x 81)
    float* sekw  = sm + 5832;          // 729
    float* sekb  = sekw + 729;         // 81
    float* stage = sekb + 81;          // 8 warps * 1296 (ks 648 | k1st 648)

    const int bb   = blockIdx.x;
    const int b    = bb >> 3;
    const int band = bb & 7;
    const int chlo = band << 6;
    const int tid  = threadIdx.x;
    const int warp = tid >> 5;
    const int lane = tid & 31;
    const float* xb = x + (size_t)b * NFLAT;

    {
        const int gbase = (chlo - 4) * NHW;
        for (int i = tid; i < 5832; i += 256) {
            const int g = gbase + i;
            Xs[i] = ((unsigned)g < (unsigned)NFLAT) ? xb[g] : 0.f;
        }
        for (int i = tid; i < 729; i += 256) sekw[i] = se_key_w[i];
        if (tid < 81) sekb[tid] = se_key_b[tid];
    }
    __syncthreads();

    const float alpha = alpha_p[0];
    const float oma   = 1.0f - alpha;

    const int g_head = (chlo >> 3) + warp;
    const int chbase = chlo + warp * 8;
    float* ks   = stage + warp * 1296;
    float* k1st = ks + 648;

    #pragma unroll
    for (int l = 0; l < 8; l++) {
        const int ch = chbase + l;
        const int lr = warp*8 + l + 4;
        const float* Xc = Xs + lr * NHW;
        float wkv[9], wks[9];
        #pragma unroll
        for (int k = 0; k < 9; k++) wkv[k] = __ldg(se_val_w + ch*9 + k);
        #pragma unroll
        for (int k = 0; k < 9; k++) wks[k] = __ldg(sa_key_w + ch*9 + k);
        const float vbias = __ldg(se_val_b + ch);
        const float gam = __ldg(sa_key_bn + ch);
        const float bet = __ldg(sa_key_bn + 512 + ch);
        const float mea = __ldg(sa_key_bn + 1024 + ch);
        const float var = __ldg(sa_key_bn + 1536 + ch);
        const float s   = gam * rsqrtf(var + EPSV);
        const float sh  = bet - mea * s;

        float* gk = g_k1 + (size_t)b * NFLAT + ch * NHW;
        float* gv = g_v  + (size_t)b * NFLAT + ch * NHW;

        #pragma unroll
        for (int t = 0; t < 3; t++) {
            const int p = lane + 32 * t;
            if (p < 81) {
                float acc = sekb[p];
                #pragma unroll
                for (int d = 0; d < 9; d++)
                    acc = fmaf(sekw[p*9 + d], Xs[(lr - 4 + d)*NHW + p], acc);
                gk[p] = acc;
                k1st[l*81 + p] = acc;

                const int h = p / 9, w = p - h * 9;
                float va = vbias, sa = 0.f;
                #pragma unroll
                for (int kh = 0; kh < 3; kh++) {
                    const int hh = h + kh - 1;
                    if ((unsigned)hh < 9u) {
                        #pragma unroll
                        for (int kw = 0; kw < 3; kw++) {
                            const int ww = w + kw - 1;
                            if ((unsigned)ww < 9u) {
                                const float xv = Xc[hh*9 + ww];
                                va = fmaf(wkv[kh*3+kw], xv, va);
                                sa = fmaf(wks[kh*3+kw], xv, sa);
                            }
                        }
                    }
                }
                gv[p] = va;
                ks[l*81 + p] = fmaxf(fmaf(sa, s, sh), 0.f);
            }
        }
    }
    __syncwarp();

    const float bg = __ldg(sa_att_b2 + g_head);
    float a2b[3] = {bg, bg, bg};
    #pragma unroll
    for (int o = 0; o < 8; o++) {
        const int oc = chbase + o;
        float w1r[16];
        #pragma unroll
        for (int i = 0; i < 16; i++) w1r[i] = __ldg(sa_att_w1 + oc*16 + i);
        const float gam = __ldg(sa_att_bn + oc);
        const float bet = __ldg(sa_att_bn + 512 + oc);
        const float mea = __ldg(sa_att_bn + 1024 + oc);
        const float var = __ldg(sa_att_bn + 1536 + oc);
        const float s2  = gam * rsqrtf(var + EPSV);
        const float sh2 = bet - mea * s2;
        const float w2v = __ldg(sa_att_w2 + oc);
        #pragma unroll
        for (int t = 0; t < 3; t++) {
            const int pp = lane + 32 * t;
            if (pp < 81) {
                float aa = 0.f;
                #pragma unroll
                for (int l = 0; l < 8; l++) {
                    aa = fmaf(w1r[2*l],   ks[l*81 + pp], aa);
                    aa = fmaf(w1r[2*l+1], Xs[(warp*8 + l + 4)*NHW + pp], aa);
                }
                aa = fmaxf(fmaf(aa, s2, sh2), 0.f);
                a2b[t] = fmaf(w2v, aa, a2b[t]);
            }
        }
    }

    float m = -1e30f;
    #pragma unroll
    for (int t = 0; t < 3; t++) { if (lane + 32*t < 81) m = fmaxf(m, a2b[t]); }
    #pragma unroll
    for (int off = 16; off > 0; off >>= 1)
        m = fmaxf(m, __shfl_xor_sync(0xffffffffu, m, off));
    float ex[3] = {0.f, 0.f, 0.f};
    float ssum = 0.f;
    #pragma unroll
    for (int t = 0; t < 3; t++) {
        const int pp = lane + 32 * t;
        if (pp < 81) { ex[t] = __expf(a2b[t] - m); ssum += ex[t]; }
    }
    #pragma unroll
    for (int off = 16; off > 0; off >>= 1)
        ssum += __shfl_xor_sync(0xffffffffu, ssum, off);
    const float inv = 1.0f / ssum;

    #pragma unroll
    for (int t = 0; t < 3; t++) {
        const int pp = lane + 32 * t;
        if (pp < 81) {
            const float att = ex[t] * inv;
            #pragma unroll
            for (int l = 0; l < 8; l++) {
                const int ch = chbase + l;
                const float o2 = ks[l*81 + pp]
                               + att * Xs[(warp*8 + l + 4)*NHW + pp];
                out[(size_t)b * NFLAT + ch*NHW + pp]
                    = oma * o2 + alpha * k1st[l*81 + pp];
            }
        }
    }
}

// ---------------------------------------------------------------------------
// Kernel B: grid = NB*2 (batch x column-half). Per CTA: 81x162x256 GEMM,
// thread tile 9o x 8ch (cols lane*4 and 128+lane*4), 288 threads (9 warps,
// o uniform per warp -> W1T broadcast). cp.async double-buffered tiles.
// Then BN+relu, phased w2 contraction, 9-tap softmax, smem-v epilogue.
// smem floats: W1T[13124] | sbuf[2*4608] | a2s[2304] | w2s[729] | bn[162]
// Epilogue aliases [0 .. 21384) (W1T+sbuf region) for the 264x81 v band.
// ---------------------------------------------------------------------------
#define OFFB_W1T 0
#define OFFB_SRC 13124
#define OFFB_A2S (OFFB_SRC + 9216)     // 22340
#define OFFB_W2  (OFFB_A2S + 2304)     // 24644
#define OFFB_BNS (OFFB_W2 + 729)       // 25373
#define OFFB_BNH (OFFB_BNS + 81)       // 25454
#define B_SMEM_FLOATS (OFFB_BNH + 81)  // 25535

__global__ __launch_bounds__(288, 2)
void dmuca_kernelB(const float* __restrict__ x,
                   const float* __restrict__ alpha_p,
                   const float* __restrict__ se_att_w1,
                   const float* __restrict__ se_att_bn,
                   const float* __restrict__ se_att_w2,
                   const float* __restrict__ se_att_b2,
                   float* __restrict__ out)
{
    extern __shared__ float sm[];
    float* W1T  = sm + OFFB_W1T;
    float* sbuf = sm + OFFB_SRC;
    float* a2s  = sm + OFFB_A2S;
    float* w2s  = sm + OFFB_W2;
    float* bnS  = sm + OFFB_BNS;
    float* bnH  = sm + OFFB_BNH;
    float* vsm  = sm;                    // epilogue alias: 264*81 = 21384

    const int bx  = blockIdx.x;
    const int b   = bx >> 1;
    const int hf  = bx & 1;
    const int cbase = hf << 8;           // 0 or 256
    const int tid = threadIdx.x;
    const int lane = tid & 31;
    const int wrp  = tid >> 5;           // 0..8 == o-group
    const float* xb  = x    + (size_t)b * NFLAT + cbase;
    const float* k1b = g_k1 + (size_t)b * NFLAT + cbase;
    const float* vb  = g_v  + (size_t)b * NFLAT;

    const uint32_t sb_base = (uint32_t)__cvta_generic_to_shared(sbuf);

    // prologue: smem fills
    for (int i = tid; i < 13122; i += 288) {
        const int j = i / 81, o = i - j * 81;
        W1T[i] = __ldg(se_att_w1 + o * 162 + j);
    }
    for (int i = tid; i < 729; i += 288) w2s[i] = se_att_w2[i];
    if (tid < 81) {
        const float gam = se_att_bn[tid],       bet = se_att_bn[81 + tid];
        const float mea = se_att_bn[162 + tid], var = se_att_bn[243 + tid];
        const float s = gam * rsqrtf(var + EPSV);
        bnS[tid] = s; bnH[tid] = bet - mea * s;
    }
    for (int i = tid; i < 2304; i += 288) a2s[i] = __ldg(se_att_b2 + (i >> 8));

    const int o0  = wrp * 9;             // 9 o-rows
    const int chA = lane * 4;            // cols chA..chA+3 and 128+chA..+3

    u64 acc2[9][4];
    #pragma unroll
    for (int a = 0; a < 9; a++)
        #pragma unroll
        for (int q = 0; q < 4; q++) acc2[a][q] = 0ULL;

    // issue tile 0
    {
        #pragma unroll
        for (int q = 0; q < 4; q++) {
            const int f4 = q * 288 + tid;          // 0..1151
            const int jr = f4 >> 6, c4 = f4 & 63;  // 64 float4 per 256f row
            const float* row = (jr < 81) ? (xb + jr*512) : (k1b + (jr-81)*512);
            cp_async16(sb_base + (uint32_t)((jr*256 + c4*4) * 4),
                       (const void*)(row + c4*4));
        }
        cp_commit();
    }

    for (int kt = 0; kt < 9; kt++) {
        if (kt < 8) {
            const uint32_t bufoff = (uint32_t)(((kt+1) & 1) * 4608 * 4);
            #pragma unroll
            for (int q = 0; q < 4; q++) {
                const int f4 = q * 288 + tid;
                const int jr = f4 >> 6, c4 = f4 & 63;
                const int j  = (kt+1)*18 + jr;
                const float* row = (j < 81) ? (xb + j*512) : (k1b + (j-81)*512);
                cp_async16(sb_base + bufoff + (uint32_t)((jr*256 + c4*4) * 4),
                           (const void*)(row + c4*4));
            }
            cp_commit();
            cp_wait<1>();
        } else {
            cp_wait<0>();
        }
        __syncthreads();

        const float* sb = sbuf + (kt & 1) * 4608;
        const ulonglong2* sb2 = (const ulonglong2*)sb;   // 64 per 256f row
        const float* wrow = W1T + (size_t)kt * 18 * 81 + o0;
        for (int jj = 0; jj < 18; jj++) {
            const ulonglong2 pA = sb2[jj * 64 + lane];        // cols chA..+3
            const ulonglong2 pB = sb2[jj * 64 + 32 + lane];   // cols 128+chA..
            const float* wj = wrow + jj * 81;
            #pragma unroll
            for (int a = 0; a < 9; a++) {
                const float wv = wj[a];
                const u64 wv2 = pack2(wv, wv);
                ffma2(acc2[a][0], wv2, pA.x);
                ffma2(acc2[a][1], wv2, pA.y);
                ffma2(acc2[a][2], wv2, pB.x);
                ffma2(acc2[a][3], wv2, pB.y);
            }
        }
        __syncthreads();
    }

    // BN + relu -> accf[a][0..7]; cols: k<4 -> chA+k, k>=4 -> 128+chA+k-4
    float accf[9][8];
    #pragma unroll
    for (int a = 0; a < 9; a++) {
        const float s = bnS[o0 + a], hh = bnH[o0 + a];
        #pragma unroll
        for (int q = 0; q < 4; q++) {
            float lo, hi;
            unpack2(acc2[a][q], lo, hi);
            accf[a][2*q]   = fmaxf(fmaf(lo, s, hh), 0.f);
            accf[a][2*q+1] = fmaxf(fmaf(hi, s, hh), 0.f);
        }
    }

    // stage-2: a2s[d, col] += sum_a w2[d, o0+a] * accf[a][col]; one warp per
    // barrier phase (deterministic)
    for (int ot = 0; ot < 9; ot++) {
        if (wrp == ot) {
            #pragma unroll
            for (int d = 0; d < 9; d++) {
                float w2r[9];
                #pragma unroll
                for (int a = 0; a < 9; a++) w2r[a] = w2s[d*81 + o0 + a];
                #pragma unroll
                for (int k = 0; k < 8; k++) {
                    const int col = (k < 4) ? (chA + k) : (128 + chA + k - 4);
                    float pd = 0.f;
                    #pragma unroll
                    for (int a = 0; a < 9; a++)
                        pd = fmaf(w2r[a], accf[a][k], pd);
                    a2s[d*256 + col] += pd;
                }
            }
        }
        __syncthreads();
    }

    // softmax over the 9 spectral taps, per column, in place
    if (tid < 256) {
        const int col = tid;
        float v[9], m = -1e30f;
        #pragma unroll
        for (int d = 0; d < 9; d++) { v[d] = a2s[d*256 + col]; m = fmaxf(m, v[d]); }
        float ssum = 0.f;
        #pragma unroll
        for (int d = 0; d < 9; d++) { v[d] = __expf(v[d] - m); ssum += v[d]; }
        const float inv = 1.0f / ssum;
        #pragma unroll
        for (int d = 0; d < 9; d++) a2s[d*256 + col] = v[d] * inv;
    }
    __syncthreads();

    // stage v band into smem: local rows 0..263 = channels cbase-4 .. cbase+259
    {
        const int gbase = (cbase - 4) * NHW;
        for (int i = tid; i < 264 * NHW; i += 288) {
            const int g = gbase + i;
            vsm[i] = ((unsigned)g < (unsigned)NFLAT) ? vb[g] : 0.f;
        }
    }
    __syncthreads();

    // epilogue: out += alpha * sum_d attn[d,chl] * vsm[(chl+d)*81 + p]
    const float alpha = alpha_p[0];
    float* outb = out + (size_t)b * NFLAT + (size_t)cbase * NHW;
    for (int e = tid; e < 256 * NHW; e += 288) {
        const int chl = e / 81;
        const int p   = e - chl * 81;
        float s = 0.f;
        #pragma unroll
        for (int d = 0; d < 9; d++)
            s = fmaf(a2s[d*256 + chl], vsm[(chl + d)*81 + p], s);
        outb[e] += alpha * s;
    }
}

extern "C" void kernel_launch(void* const* d_in, const int* in_sizes, int n_in,
                              void* d_out, int out_size) {
    const float* x         = (const float*)d_in[0];
    const float* alpha     = (const float*)d_in[1];
    const float* sa_key_w  = (const float*)d_in[2];
    const float* sa_key_bn = (const float*)d_in[3];
    const float* sa_att_w1 = (const float*)d_in[4];
    const float* sa_att_bn = (const float*)d_in[5];
    const float* sa_att_w2 = (const float*)d_in[6];
    const float* sa_att_b2 = (const float*)d_in[7];
    const float* se_key_w  = (const float*)d_in[8];
    const float* se_key_b  = (const float*)d_in[9];
    const float* se_att_w1 = (const float*)d_in[10];
    const float* se_att_bn = (const float*)d_in[11];
    const float* se_att_w2 = (const float*)d_in[12];
    const float* se_att_b2 = (const float*)d_in[13];
    const float* se_val_w  = (const float*)d_in[14];
    const float* se_val_b  = (const float*)d_in[15];
    float* out = (float*)d_out;

    const int smemA = A_SMEM_FLOATS * 4;     // 68040 B
    const int smemB = B_SMEM_FLOATS * 4;     // 102140 B
    cudaFuncSetAttribute(dmuca_kernelA,
        cudaFuncAttributeMaxDynamicSharedMemorySize, smemA);
    cudaFuncSetAttribute(dmuca_kernelB,
        cudaFuncAttributeMaxDynamicSharedMemorySize, smemB);

    dmuca_kernelA<<<NB*8, 256, smemA>>>(x, alpha, sa_key_w, sa_key_bn,
                                        sa_att_w1, sa_att_bn, sa_att_w2, sa_att_b2,
                                        se_key_w, se_key_b, se_val_w, se_val_b, out);
    dmuca_kernelB<<<NB*2, 288, smemB>>>(x, alpha, se_att_w1, se_att_bn,
                                        se_att_w2, se_att_b2, out);
}

// round 8
// speedup vs baseline: 1.5638x; 1.1993x over previous
#include <cuda_runtime.h>
#include <cuda_bf16.h>
#include <cstdint>

#define NB    256
#define NC    512
#define NHW   81
#define NFLAT (NC*NHW)           // 41472 per batch
#define EPSV  1e-5f

__device__ __forceinline__ float to_tf32(float x) {
    float r; asm("cvt.rna.tf32.f32 %0, %1;" : "=f"(r) : "f"(x)); return r;
}
// m16n8k8 tf32 warp MMA (baseline PTX, sm_80+): D += A*B
__device__ __forceinline__ void mma_tf32(float c[4],
                                         uint32_t a0, uint32_t a1,
                                         uint32_t a2, uint32_t a3,
                                         uint32_t b0, uint32_t b1) {
    asm volatile("mma.sync.aligned.m16n8k8.row.col.f32.tf32.tf32.f32 "
                 "{%0,%1,%2,%3}, {%4,%5,%6,%7}, {%8,%9}, {%0,%1,%2,%3};"
                 : "+f"(c[0]), "+f"(c[1]), "+f"(c[2]), "+f"(c[3])
                 : "r"(a0), "r"(a1), "r"(a2), "r"(a3), "r"(b0), "r"(b1));
}

// Global scratch (allocation-free rule: __device__ arrays)
__device__ __align__(16) float g_k1[(size_t)NB * NFLAT];  // SeMCA key
__device__ __align__(16) float g_v [(size_t)NB * NFLAT];  // SeMCA value (dw3x3)

// ---------------------------------------------------------------------------
// Kernel A (banded): unchanged (passing since round 5).
// ---------------------------------------------------------------------------
#define A_SMEM_FLOATS (5832 + 729 + 81 + 8*1296)   // 17010

__global__ __launch_bounds__(256, 3)
void dmuca_kernelA(const float* __restrict__ x,
                   const float* __restrict__ alpha_p,
                   const float* __restrict__ sa_key_w,
                   const float* __restrict__ sa_key_bn,
                   const float* __restrict__ sa_att_w1,
                   const float* __restrict__ sa_att_bn,
                   const float* __restrict__ sa_att_w2,
                   const float* __restrict__ sa_att_b2,
                   const float* __restrict__ se_key_w,
                   const float* __restrict__ se_key_b,
                   const float* __restrict__ se_val_w,
                   const float* __restrict__ se_val_b,
                   float* __restrict__ out)
{
    extern __shared__ float sm[];
    float* Xs    = sm;
    float* sekw  = sm + 5832;
    float* sekb  = sekw + 729;
    float* stage = sekb + 81;

    const int bb   = blockIdx.x;
    const int b    = bb >> 3;
    const int band = bb & 7;
    const int chlo = band << 6;
    const int tid  = threadIdx.x;
    const int warp = tid >> 5;
    const int lane = tid & 31;
    const float* xb = x + (size_t)b * NFLAT;

    {
        const int gbase = (chlo - 4) * NHW;
        for (int i = tid; i < 5832; i += 256) {
            const int g = gbase + i;
            Xs[i] = ((unsigned)g < (unsigned)NFLAT) ? xb[g] : 0.f;
        }
        for (int i = tid; i < 729; i += 256) sekw[i] = se_key_w[i];
        if (tid < 81) sekb[tid] = se_key_b[tid];
    }
    __syncthreads();

    const float alpha = alpha_p[0];
    const float oma   = 1.0f - alpha;

    const int g_head = (chlo >> 3) + warp;
    const int chbase = chlo + warp * 8;
    float* ks   = stage + warp * 1296;
    float* k1st = ks + 648;

    #pragma unroll
    for (int l = 0; l < 8; l++) {
        const int ch = chbase + l;
        const int lr = warp*8 + l + 4;
        const float* Xc = Xs + lr * NHW;
        float wkv[9], wks[9];
        #pragma unroll
        for (int k = 0; k < 9; k++) wkv[k] = __ldg(se_val_w + ch*9 + k);
        #pragma unroll
        for (int k = 0; k < 9; k++) wks[k] = __ldg(sa_key_w + ch*9 + k);
        const float vbias = __ldg(se_val_b + ch);
        const float gam = __ldg(sa_key_bn + ch);
        const float bet = __ldg(sa_key_bn + 512 + ch);
        const float mea = __ldg(sa_key_bn + 1024 + ch);
        const float var = __ldg(sa_key_bn + 1536 + ch);
        const float s   = gam * rsqrtf(var + EPSV);
        const float sh  = bet - mea * s;

        float* gk = g_k1 + (size_t)b * NFLAT + ch * NHW;
        float* gv = g_v  + (size_t)b * NFLAT + ch * NHW;

        #pragma unroll
        for (int t = 0; t < 3; t++) {
            const int p = lane + 32 * t;
            if (p < 81) {
                float acc = sekb[p];
                #pragma unroll
                for (int d = 0; d < 9; d++)
                    acc = fmaf(sekw[p*9 + d], Xs[(lr - 4 + d)*NHW + p], acc);
                gk[p] = acc;
                k1st[l*81 + p] = acc;

                const int h = p / 9, w = p - h * 9;
                float va = vbias, sa = 0.f;
                #pragma unroll
                for (int kh = 0; kh < 3; kh++) {
                    const int hh = h + kh - 1;
                    if ((unsigned)hh < 9u) {
                        #pragma unroll
                        for (int kw = 0; kw < 3; kw++) {
                            const int ww = w + kw - 1;
                            if ((unsigned)ww < 9u) {
                                const float xv = Xc[hh*9 + ww];
                                va = fmaf(wkv[kh*3+kw], xv, va);
                                sa = fmaf(wks[kh*3+kw], xv, sa);
                            }
                        }
                    }
                }
                gv[p] = va;
                ks[l*81 + p] = fmaxf(fmaf(sa, s, sh), 0.f);
            }
        }
    }
    __syncwarp();

    const float bg = __ldg(sa_att_b2 + g_head);
    float a2b[3] = {bg, bg, bg};
    #pragma unroll
    for (int o = 0; o < 8; o++) {
        const int oc = chbase + o;
        float w1r[16];
        #pragma unroll
        for (int i = 0; i < 16; i++) w1r[i] = __ldg(sa_att_w1 + oc*16 + i);
        const float gam = __ldg(sa_att_bn + oc);
        const float bet = __ldg(sa_att_bn + 512 + oc);
        const float mea = __ldg(sa_att_bn + 1024 + oc);
        const float var = __ldg(sa_att_bn + 1536 + oc);
        const float s2  = gam * rsqrtf(var + EPSV);
        const float sh2 = bet - mea * s2;
        const float w2v = __ldg(sa_att_w2 + oc);
        #pragma unroll
        for (int t = 0; t < 3; t++) {
            const int pp = lane + 32 * t;
            if (pp < 81) {
                float aa = 0.f;
                #pragma unroll
                for (int l = 0; l < 8; l++) {
                    aa = fmaf(w1r[2*l],   ks[l*81 + pp], aa);
                    aa = fmaf(w1r[2*l+1], Xs[(warp*8 + l + 4)*NHW + pp], aa);
                }
                aa = fmaxf(fmaf(aa, s2, sh2), 0.f);
                a2b[t] = fmaf(w2v, aa, a2b[t]);
            }
        }
    }

    float m = -1e30f;
    #pragma unroll
    for (int t = 0; t < 3; t++) { if (lane + 32*t < 81) m = fmaxf(m, a2b[t]); }
    #pragma unroll
    for (int off = 16; off > 0; off >>= 1)
        m = fmaxf(m, __shfl_xor_sync(0xffffffffu, m, off));
    float ex[3] = {0.f, 0.f, 0.f};
    float ssum = 0.f;
    #pragma unroll
    for (int t = 0; t < 3; t++) {
        const int pp = lane + 32 * t;
        if (pp < 81) { ex[t] = __expf(a2b[t] - m); ssum += ex[t]; }
    }
    #pragma unroll
    for (int off = 16; off > 0; off >>= 1)
        ssum += __shfl_xor_sync(0xffffffffu, ssum, off);
    const float inv = 1.0f / ssum;

    #pragma unroll
    for (int t = 0; t < 3; t++) {
        const int pp = lane + 32 * t;
        if (pp < 81) {
            const float att = ex[t] * inv;
            #pragma unroll
            for (int l = 0; l < 8; l++) {
                const int ch = chbase + l;
                const float o2 = ks[l*81 + pp]
                               + att * Xs[(warp*8 + l + 4)*NHW + pp];
                out[(size_t)b * NFLAT + ch*NHW + pp]
                    = oma * o2 + alpha * k1st[l*81 + pp];
            }
        }
    }
}

// ---------------------------------------------------------------------------
// Kernel B (warp-MMA tf32): grid = NB, 512 threads, one batch per CTA.
// C^T[512,88] = S^T[512,176] @ W1^T[176,88]; S = [x rows 0..80 | k1 rows 81..161].
// Data operand split hi/lo (2 MMAs per k-step), W1 single tf32.
// 2 passes: warp owns m16 x n88 tile; logits (bn+relu+w2) folded into the
// register epilogue with a 4-lane shfl reduce. Then softmax + v-band + out.
//
// smem floats: SH[512*17]@0 | SL@8704 | W1f[176*104]@17408 (ends 35712)
//              vsm alias @0 (520*81=42120) | a2s@42120 (4608) | w2s@46728 (729)
//              bnS@47457 (81) | bnH@47538 (81)   total 47619 fl = 190476 B
// ---------------------------------------------------------------------------
#define FB_SH   0
#define FB_SL   8704
#define FB_W1F  17408
#define FB_A2S  42120
#define FB_W2   46728
#define FB_BNS  47457
#define FB_BNH  47538
#define B_SMEM_FLOATS 47619

__global__ __launch_bounds__(512, 1)
void dmuca_kernelB(const float* __restrict__ x,
                   const float* __restrict__ alpha_p,
                   const float* __restrict__ se_att_w1,
                   const float* __restrict__ se_att_bn,
                   const float* __restrict__ se_att_w2,
                   const float* __restrict__ se_att_b2,
                   float* __restrict__ out)
{
    extern __shared__ float sm[];
    float* SH  = sm + FB_SH;    // [n=512][k=16] stride 17, tf32-hi of S^T
    float* SL  = sm + FB_SL;    // tf32-lo
    float* W1f = sm + FB_W1F;   // [j=176][o=104] stride 104, tf32
    float* vsm = sm;            // epilogue alias, 520*81
    float* a2s = sm + FB_A2S;
    float* w2s = sm + FB_W2;
    float* bnS = sm + FB_BNS;
    float* bnH = sm + FB_BNH;

    const int b    = blockIdx.x;
    const int tid  = threadIdx.x;
    const int warp = tid >> 5;
    const int lane = tid & 31;
    const int gid  = lane >> 2;       // 0..7
    const int tig  = lane & 3;        // 0..3
    const float* xb  = x    + (size_t)b * NFLAT;
    const float* k1b = g_k1 + (size_t)b * NFLAT;

    // one-time staging: W1f (tf32, zero-padded), w2s, bn scale/shift
    for (int i = tid; i < 176*104; i += 512) {
        const int k = i / 104, o = i - k * 104;
        const float w = (o < 81 && k < 162) ? __ldg(se_att_w1 + o*162 + k) : 0.f;
        W1f[i] = to_tf32(w);
    }
    for (int i = tid; i < 729; i += 512) w2s[i] = se_att_w2[i];
    if (tid < 81) {
        const float gam = se_att_bn[tid],       bet = se_att_bn[81 + tid];
        const float mea = se_att_bn[162 + tid], var = se_att_bn[243 + tid];
        const float s = gam * rsqrtf(var + EPSV);
        bnS[tid] = s; bnH[tid] = bet - mea * s;
    }

    // S^T chunk loader: 16 k-rows x 512 n-cols; thread = (kk = tid>>5, n0 = tid&31)
    const int kk = tid >> 5;
    const int n0 = tid & 31;
    float r[16];
    {   // prefetch chunk 0 (j = kk < 81 -> x)
        const float* row = xb + kk * 512;
        #pragma unroll
        for (int i = 0; i < 16; i++) r[i] = row[n0 + 32*i];
    }

    for (int pass = 0; pass < 2; pass++) {
        const int m0 = (warp + 16 * pass) << 4;    // channel base, 0..496

        float acc[11][4];
        #pragma unroll
        for (int nb = 0; nb < 11; nb++)
            #pragma unroll
            for (int e = 0; e < 4; e++) acc[nb][e] = 0.f;

        for (int kc = 0; kc < 11; kc++) {
            __syncthreads();      // prior compute done reading SH/SL
            #pragma unroll
            for (int i = 0; i < 16; i++) {
                const float v  = r[i];
                const float hi = to_tf32(v);
                const float lo = to_tf32(v - hi);
                const int   n  = n0 + 32*i;
                SH[n*17 + kk] = hi;
                SL[n*17 + kk] = lo;
            }
            __syncthreads();

            // prefetch next chunk (wraps to chunk 0 for pass 1)
            if (!(pass == 1 && kc == 10)) {
                const int nkc = (kc < 10) ? kc + 1 : 0;
                const int j = nkc * 16 + kk;
                if (j < 81) {
                    const float* row = xb + j * 512;
                    #pragma unroll
                    for (int i = 0; i < 16; i++) r[i] = row[n0 + 32*i];
                } else if (j < 162) {
                    const float* row = k1b + (j - 81) * 512;
                    #pragma unroll
                    for (int i = 0; i < 16; i++) r[i] = row[n0 + 32*i];
                } else {
                    #pragma unroll
                    for (int i = 0; i < 16; i++) r[i] = 0.f;
                }
            }

            // compute: 2 k8-steps over this chunk
            #pragma unroll
            for (int ks = 0; ks < 2; ks++) {
                const int kl = ks * 8 + tig;
                const int jr = kc * 16 + kl;
                const uint32_t ah0 = __float_as_uint(SH[(m0+gid  )*17 + kl]);
                const uint32_t ah1 = __float_as_uint(SH[(m0+gid+8)*17 + kl]);
                const uint32_t ah2 = __float_as_uint(SH[(m0+gid  )*17 + kl + 4]);
                const uint32_t ah3 = __float_as_uint(SH[(m0+gid+8)*17 + kl + 4]);
                const uint32_t al0 = __float_as_uint(SL[(m0+gid  )*17 + kl]);
                const uint32_t al1 = __float_as_uint(SL[(m0+gid+8)*17 + kl]);
                const uint32_t al2 = __float_as_uint(SL[(m0+gid  )*17 + kl + 4]);
                const uint32_t al3 = __float_as_uint(SL[(m0+gid+8)*17 + kl + 4]);
                const float* wr0 = W1f + (size_t)jr * 104;        // k-row tig
                const float* wr1 = W1f + (size_t)(jr + 4) * 104;  // k-row tig+4
                #pragma unroll
                for (int nb = 0; nb < 11; nb++) {
                    const uint32_t b0 = __float_as_uint(wr0[nb*8 + gid]);
                    const uint32_t b1 = __float_as_uint(wr1[nb*8 + gid]);
                    mma_tf32(acc[nb], ah0, ah1, ah2, ah3, b0, b1);
                    mma_tf32(acc[nb], al0, al1, al2, al3, b0, b1);
                }
            }
        }

        // register epilogue: bn+relu+w2 -> logits for channels m0+gid, m0+gid+8
        float lg[2][9];
        #pragma unroll
        for (int rr = 0; rr < 2; rr++)
            #pragma unroll
            for (int d = 0; d < 9; d++) lg[rr][d] = 0.f;
        #pragma unroll
        for (int nb = 0; nb < 11; nb++) {
            #pragma unroll
            for (int e = 0; e < 4; e++) {
                const int o = nb*8 + tig*2 + (e & 1);
                if (o < 81) {
                    const float a1 = fmaxf(fmaf(acc[nb][e], bnS[o], bnH[o]), 0.f);
                    const int rr = e >> 1;
                    #pragma unroll
                    for (int d = 0; d < 9; d++)
                        lg[rr][d] = fmaf(w2s[d*81 + o], a1, lg[rr][d]);
                }
            }
        }
        #pragma unroll
        for (int rr = 0; rr < 2; rr++)
            #pragma unroll
            for (int d = 0; d < 9; d++) {
                lg[rr][d] += __shfl_xor_sync(0xffffffffu, lg[rr][d], 1);
                lg[rr][d] += __shfl_xor_sync(0xffffffffu, lg[rr][d], 2);
            }
        if (tig == 0) {
            #pragma unroll
            for (int d = 0; d < 9; d++) {
                const float bias = __ldg(se_att_b2 + d);
                a2s[d*512 + m0 + gid]     = lg[0][d] + bias;
                a2s[d*512 + m0 + gid + 8] = lg[1][d] + bias;
            }
        }
    }
    __syncthreads();

    // softmax over the 9 spectral taps, per column
    {
        const int n = tid;
        float v[9], mx = -1e30f;
        #pragma unroll
        for (int d = 0; d < 9; d++) { v[d] = a2s[d*512 + n]; mx = fmaxf(mx, v[d]); }
        float ssum = 0.f;
        #pragma unroll
        for (int d = 0; d < 9; d++) { v[d] = __expf(v[d] - mx); ssum += v[d]; }
        const float inv = 1.0f / ssum;
        #pragma unroll
        for (int d = 0; d < 9; d++) a2s[d*512 + n] = v[d] * inv;
    }
    __syncthreads();   // all SH/SL reads long done; safe to overwrite with vsm

    // stage v band (rows = channels -4..515, zero-filled)
    {
        const float* vb = g_v + (size_t)b * NFLAT;
        for (int i = tid; i < 520 * NHW; i += 512) {
            const int g = i - 4 * NHW;
            vsm[i] = ((unsigned)g < (unsigned)NFLAT) ? vb[g] : 0.f;
        }
    }
    __syncthreads();

    // out += alpha * sum_d attn[d,ch] * v[ch+d-4, p]
    const float alpha = alpha_p[0];
    float* outb = out + (size_t)b * NFLAT;
    int ch = tid / 81;
    int p  = tid - ch * 81;
    for (int e = tid; e < NFLAT; e += 512) {
        float s = 0.f;
        #pragma unroll
        for (int d = 0; d < 9; d++)
            s = fmaf(a2s[d*512 + ch], vsm[(ch + d)*81 + p], s);
        outb[e] += alpha * s;
        p += 26; ch += 6;                 // advance by 512 = 6*81 + 26
        if (p >= 81) { p -= 81; ch += 1; }
    }
}

extern "C" void kernel_launch(void* const* d_in, const int* in_sizes, int n_in,
                              void* d_out, int out_size) {
    const float* x         = (const float*)d_in[0];
    const float* alpha     = (const float*)d_in[1];
    const float* sa_key_w  = (const float*)d_in[2];
    const float* sa_key_bn = (const float*)d_in[3];
    const float* sa_att_w1 = (const float*)d_in[4];
    const float* sa_att_bn = (const float*)d_in[5];
    const float* sa_att_w2 = (const float*)d_in[6];
    const float* sa_att_b2 = (const float*)d_in[7];
    const float* se_key_w  = (const float*)d_in[8];
    const float* se_key_b  = (const float*)d_in[9];
    const float* se_att_w1 = (const float*)d_in[10];
    const float* se_att_bn = (const float*)d_in[11];
    const float* se_att_w2 = (const float*)d_in[12];
    const float* se_att_b2 = (const float*)d_in[13];
    const float* se_val_w  = (const float*)d_in[14];
    const float* se_val_b  = (const float*)d_in[15];
    float* out = (float*)d_out;

    const int smemA = A_SMEM_FLOATS * 4;     // 68040 B
    const int smemB = B_SMEM_FLOATS * 4;     // 190476 B
    cudaFuncSetAttribute(dmuca_kernelA,
        cudaFuncAttributeMaxDynamicSharedMemorySize, smemA);
    cudaFuncSetAttribute(dmuca_kernelB,
        cudaFuncAttributeMaxDynamicSharedMemorySize, smemB);

    dmuca_kernelA<<<NB*8, 256, smemA>>>(x, alpha, sa_key_w, sa_key_bn,
                                        sa_att_w1, sa_att_bn, sa_att_w2, sa_att_b2,
                                        se_key_w, se_key_b, se_val_w, se_val_b, out);
    dmuca_kernelB<<<NB, 512, smemB>>>(x, alpha, se_att_w1, se_att_bn,
                                      se_att_w2, se_att_b2, out);
}